// round 7
// baseline (speedup 1.0000x reference)
#include <cuda_runtime.h>
#include <cuda_bf16.h>
#include <cstdint>

#define TT 32
#define NN 20000
#define CC 10

// ---------------- SMEM layout (bytes) ----------------
#define WHH_HI 0          /* bf16 [128][128] swizzled */
#define WHH_LO 32768
#define H_HI   65536      /* bf16 [144][128] swizzled */
#define H_LO   102400
#define X_HI   139264     /* stages Wih_hi at init; then x_hi; then OUTS overlay */
#define X_LO   176128     /* stages Wih_lo at init; then x_lo */
#define RED_O  212992     /* float2 [8][144] (s1,s2) */
#define LP_O   222208     /* float  [8][144] */
#define RAB_O  226816     /* float  [144]  (w = e*rstd) */
#define SCAL_O 227968     /* float[2]: S1, S2 */
#define WGS_O  227976     /* float[10] */
#define WB_O   228016     /* float[10] */
#define SMEMSZ 228064

// ---------------------------------------------------------------------------
__device__ __forceinline__ uint32_t smem_u32_of(const void* p) {
    uint32_t a;
    asm("{ .reg .u64 t; cvta.to.shared.u64 t, %1; cvt.u32.u64 %0, t; }" : "=r"(a) : "l"(p));
    return a;
}
__device__ __forceinline__ void mma_bf16(float* c, const uint32_t* a, const uint32_t* b) {
    asm volatile("mma.sync.aligned.m16n8k16.row.col.f32.bf16.bf16.f32 "
        "{%0,%1,%2,%3}, {%4,%5,%6,%7}, {%8,%9}, {%0,%1,%2,%3};"
        : "+f"(c[0]), "+f"(c[1]), "+f"(c[2]), "+f"(c[3])
        : "r"(a[0]), "r"(a[1]), "r"(a[2]), "r"(a[3]), "r"(b[0]), "r"(b[1]));
}
__device__ __forceinline__ void ldsm4(uint32_t* r, uint32_t addr) {
    asm volatile("ldmatrix.sync.aligned.m8n8.x4.shared.b16 {%0,%1,%2,%3}, [%4];"
        : "=r"(r[0]), "=r"(r[1]), "=r"(r[2]), "=r"(r[3]) : "r"(addr));
}
__device__ __forceinline__ void ldsm2(uint32_t* r, uint32_t addr) {
    asm volatile("ldmatrix.sync.aligned.m8n8.x2.shared.b16 {%0,%1}, [%2];"
        : "=r"(r[0]), "=r"(r[1]) : "r"(addr));
}
// swizzled byte offset in a [rows][128] bf16 tile (256 B/row)
__device__ __forceinline__ uint32_t hswz(int r, int k) {
    int k8 = k >> 3;
    int s = (k8 & 8) | ((k8 ^ r) & 7);
    return (uint32_t)(r * 256 + s * 16 + (k & 7) * 2);
}
__device__ __forceinline__ uint32_t packbf(float a, float b) {
    uint32_t p;
    asm("cvt.rn.bf16x2.f32 %0, %1, %2;" : "=r"(p) : "f"(b), "f"(a));
    return p;
}
__device__ __forceinline__ void conv_weight(const float* __restrict__ W,
                                            char* hi, char* lo, int tid) {
    for (int idx = tid; idx < 16384; idx += 256) {
        int r = idx >> 7, k = idx & 127;
        float w = W[idx];
        __nv_bfloat16 wh = __float2bfloat16(w);
        uint32_t o = hswz(r, k);
        *(__nv_bfloat16*)(hi + o) = wh;
        *(__nv_bfloat16*)(lo + o) = __float2bfloat16(w - __bfloat162float(wh));
    }
}

// ===========================================================================
// Single fused kernel: 144 rows/CTA, grid 139 (one wave), 8 warps x n16.
// ===========================================================================
__global__ __launch_bounds__(256, 1) void grn_one(
    const float* __restrict__ X,
    const float* __restrict__ W_ih,  const float* __restrict__ W_hh,
    const float* __restrict__ b_ih,  const float* __restrict__ b_hh,
    const float* __restrict__ ln_g,  const float* __restrict__ ln_b,
    const float* __restrict__ attn_W, const float* __restrict__ attn_b,
    const float* __restrict__ dense_W, const float* __restrict__ dense_b,
    float* __restrict__ out)
{
    extern __shared__ char sm[];
    const uint32_t sb = smem_u32_of(sm);
    const int tid = threadIdx.x, warp = tid >> 5, lane = tid & 31;
    const int g = lane >> 2, q4 = lane & 3;
    const int nw = warp * 16;
    const int n0 = blockIdx.x * 144;
    const int cA = nw + q4 * 2;
    const int ar = lane & 15;
    const int akbase = ((lane >> 4) << 3);
    const int bn = nw + (lane & 7);
    const int bkoff = (((lane >> 3) & 1) << 3);

    // ---- stage weights: Wih -> X region (temp), Whh -> its tiles ----
    conv_weight(W_ih, sm + X_HI, sm + X_LO, tid);
    conv_weight(W_hh, sm + WHH_HI, sm + WHH_LO, tid);
    if (tid == 0) {
        float s1 = 0.f, s2 = 0.f;
        for (int c = 0; c < 128; c++) {
            s1 += attn_W[c] * ln_g[c];
            s2 += attn_W[c] * ln_b[c];
        }
        ((float*)(sm + SCAL_O))[0] = s1;
        ((float*)(sm + SCAL_O))[1] = s2 + attn_b[0];
    }
    __syncthreads();

    // ---- Wih fragments -> registers ----
    uint32_t wihH[8][4], wihL[8][4];
#pragma unroll
    for (int k0 = 0; k0 < 8; k0++) {
        int bk = k0 * 16 + bkoff;
        ldsm2(&wihH[k0][0], sb + X_HI + hswz(bn, bk));
        ldsm2(&wihH[k0][2], sb + X_HI + hswz(bn + 8, bk));
        ldsm2(&wihL[k0][0], sb + X_LO + hswz(bn, bk));
        ldsm2(&wihL[k0][2], sb + X_LO + hswz(bn + 8, bk));
    }
    __syncthreads();   // staging consumed; X region now free

    float b4[4], awg4[4];
    b4[0] = b_ih[cA] + b_hh[cA];         b4[1] = b_ih[cA + 1] + b_hh[cA + 1];
    b4[2] = b_ih[cA + 8] + b_hh[cA + 8]; b4[3] = b_ih[cA + 9] + b_hh[cA + 9];
    awg4[0] = attn_W[cA] * ln_g[cA];         awg4[1] = attn_W[cA + 1] * ln_g[cA + 1];
    awg4[2] = attn_W[cA + 8] * ln_g[cA + 8]; awg4[3] = attn_W[cA + 9] * ln_g[cA + 9];
    const float S1 = ((float*)(sm + SCAL_O))[0];
    const float S2 = ((float*)(sm + SCAL_O))[1];

    // batched X load: 18 chunks/thread split into 3 batches of 6
    float4 xb[6];
    auto ldgX = [&](int t, int batch) {
#pragma unroll
        for (int j = 0; j < 6; j++) {
            int fi = tid + (batch * 6 + j) * 256;
            int lr = fi >> 5, c4 = fi & 31;
            int gr = n0 + lr; if (gr > NN - 1) gr = NN - 1;
            xb[j] = *(const float4*)(X + ((size_t)t * NN + gr) * 128 + c4 * 4);
        }
    };
    auto stsX = [&](int batch) {
#pragma unroll
        for (int j = 0; j < 6; j++) {
            int fi = tid + (batch * 6 + j) * 256;
            int lr = fi >> 5, c4 = fi & 31;
            float4 x = xb[j];
            uint32_t h0 = packbf(x.x, x.y), h1 = packbf(x.z, x.w);
            float r0 = x.x - __uint_as_float(h0 << 16);
            float r1 = x.y - __uint_as_float(h0 & 0xffff0000u);
            float r2 = x.z - __uint_as_float(h1 << 16);
            float r3 = x.w - __uint_as_float(h1 & 0xffff0000u);
            uint32_t l0 = packbf(r0, r1), l1 = packbf(r2, r3);
            *(uint2*)(sm + X_HI + hswz(lr, c4 * 4)) = make_uint2(h0, h1);
            *(uint2*)(sm + X_LO + hswz(lr, c4 * 4)) = make_uint2(l0, l1);
        }
    };
    // X[0]: all three batches up front
    ldgX(0, 0); stsX(0);
    ldgX(0, 1); stsX(1);
    ldgX(0, 2); stsX(2);
    __syncthreads();

    float acc[9][2][4];
#pragma unroll
    for (int mt = 0; mt < 9; mt++)
#pragma unroll
        for (int nt = 0; nt < 2; nt++)
#pragma unroll
            for (int i = 0; i < 4; i++) acc[mt][nt][i] = 0.f;

    // ---- h0 = X[0]@Wih^T + bias (no relu) ----
#pragma unroll
    for (int k0 = 0; k0 < 8; k0++) {
        const int akb = akbase + k0 * 16;
#pragma unroll
        for (int mt = 0; mt < 9; mt++) {
            uint32_t xh[4], xl[4];
            ldsm4(xh, sb + X_HI + hswz(mt * 16 + ar, akb));
            ldsm4(xl, sb + X_LO + hswz(mt * 16 + ar, akb));
            mma_bf16(acc[mt][0], xh, &wihH[k0][0]);
            mma_bf16(acc[mt][1], xh, &wihH[k0][2]);
            mma_bf16(acc[mt][0], xh, &wihL[k0][0]);
            mma_bf16(acc[mt][1], xh, &wihL[k0][2]);
            mma_bf16(acc[mt][0], xl, &wihH[k0][0]);
            mma_bf16(acc[mt][1], xl, &wihH[k0][2]);
        }
    }
#pragma unroll
    for (int mt = 0; mt < 9; mt++)
#pragma unroll
        for (int rh = 0; rh < 2; rh++) {
            int r = mt * 16 + g + rh * 8;
            float v0 = acc[mt][0][rh * 2] + b4[0], v1 = acc[mt][0][rh * 2 + 1] + b4[1];
            float v2 = acc[mt][1][rh * 2] + b4[2], v3 = acc[mt][1][rh * 2 + 1] + b4[3];
            uint32_t p0 = packbf(v0, v1), p1 = packbf(v2, v3);
            *(uint32_t*)(sm + H_HI + hswz(r, cA)) = p0;
            *(uint32_t*)(sm + H_HI + hswz(r, cA + 8)) = p1;
            uint32_t l0 = packbf(v0 - __uint_as_float(p0 << 16),
                                 v1 - __uint_as_float(p0 & 0xffff0000u));
            uint32_t l1 = packbf(v2 - __uint_as_float(p1 << 16),
                                 v3 - __uint_as_float(p1 & 0xffff0000u));
            *(uint32_t*)(sm + H_LO + hswz(r, cA)) = l0;
            *(uint32_t*)(sm + H_LO + hswz(r, cA + 8)) = l1;
        }
    __syncthreads();

    float P[9][2][4];
#pragma unroll
    for (int mt = 0; mt < 9; mt++)
#pragma unroll
        for (int nt = 0; nt < 2; nt++)
#pragma unroll
            for (int i = 0; i < 4; i++) P[mt][nt][i] = 0.f;
    float rs_s = 0.f, rs_q = 0.f;   // unnormalized softmax sums (tid<144)

    // =================== time loop ===================
    for (int t = 0; t < TT; t++) {
        const bool more = (t < TT - 1);
#pragma unroll
        for (int mt = 0; mt < 9; mt++)
#pragma unroll
            for (int nt = 0; nt < 2; nt++)
#pragma unroll
                for (int i = 0; i < 4; i++) acc[mt][nt][i] = 0.f;

        // combined mma: acc = h@Whh^T + X[t]@Wih^T (6 split-bf16 products)
#pragma unroll
        for (int k0 = 0; k0 < 8; k0++) {
            int bk = k0 * 16 + bkoff;
            uint32_t bh0[2], bh1[2], bl0[2], bl1[2];
            ldsm2(bh0, sb + WHH_HI + hswz(bn, bk));
            ldsm2(bh1, sb + WHH_HI + hswz(bn + 8, bk));
            ldsm2(bl0, sb + WHH_LO + hswz(bn, bk));
            ldsm2(bl1, sb + WHH_LO + hswz(bn + 8, bk));
            const int akb = akbase + k0 * 16;
#pragma unroll
            for (int mt = 0; mt < 9; mt++) {
                uint32_t hh[4], hl[4], xh[4], xl[4];
                ldsm4(hh, sb + H_HI + hswz(mt * 16 + ar, akb));
                ldsm4(hl, sb + H_LO + hswz(mt * 16 + ar, akb));
                ldsm4(xh, sb + X_HI + hswz(mt * 16 + ar, akb));
                ldsm4(xl, sb + X_LO + hswz(mt * 16 + ar, akb));
                mma_bf16(acc[mt][0], hh, bh0);
                mma_bf16(acc[mt][1], hh, bh1);
                mma_bf16(acc[mt][0], hh, bl0);
                mma_bf16(acc[mt][1], hh, bl1);
                mma_bf16(acc[mt][0], hl, bh0);
                mma_bf16(acc[mt][1], hl, bh1);
                mma_bf16(acc[mt][0], xh, &wihH[k0][0]);
                mma_bf16(acc[mt][1], xh, &wihH[k0][2]);
                mma_bf16(acc[mt][0], xh, &wihL[k0][0]);
                mma_bf16(acc[mt][1], xh, &wihL[k0][2]);
                mma_bf16(acc[mt][0], xl, &wihH[k0][0]);
                mma_bf16(acc[mt][1], xl, &wihH[k0][2]);
            }
        }
        __syncthreads();   // h & x tiles free

        if (more) ldgX(t + 1, 0);   // batch-0 LDG in flight during pack

        // h_{t+1} = relu(acc + bias); pack -> SMEM (acc dies here); partials
#pragma unroll
        for (int mt = 0; mt < 9; mt++)
#pragma unroll
            for (int rh = 0; rh < 2; rh++) {
                int r = mt * 16 + g + rh * 8;
                float v0 = fmaxf(acc[mt][0][rh * 2]     + b4[0], 0.f);
                float v1 = fmaxf(acc[mt][0][rh * 2 + 1] + b4[1], 0.f);
                float v2 = fmaxf(acc[mt][1][rh * 2]     + b4[2], 0.f);
                float v3 = fmaxf(acc[mt][1][rh * 2 + 1] + b4[3], 0.f);
                uint32_t p0 = packbf(v0, v1), p1 = packbf(v2, v3);
                *(uint32_t*)(sm + H_HI + hswz(r, cA)) = p0;
                *(uint32_t*)(sm + H_HI + hswz(r, cA + 8)) = p1;
                uint32_t l0 = packbf(v0 - __uint_as_float(p0 << 16),
                                     v1 - __uint_as_float(p0 & 0xffff0000u));
                uint32_t l1 = packbf(v2 - __uint_as_float(p1 << 16),
                                     v3 - __uint_as_float(p1 & 0xffff0000u));
                *(uint32_t*)(sm + H_LO + hswz(r, cA)) = l0;
                *(uint32_t*)(sm + H_LO + hswz(r, cA + 8)) = l1;

                float s1 = v0 + v1 + v2 + v3;
                float s2 = fmaf(v0, v0, fmaf(v1, v1, fmaf(v2, v2, v3 * v3)));
                float lp = fmaf(v0, awg4[0], fmaf(v1, awg4[1],
                           fmaf(v2, awg4[2], v3 * awg4[3])));
                s1 += __shfl_xor_sync(0xffffffffu, s1, 1);
                s1 += __shfl_xor_sync(0xffffffffu, s1, 2);
                s2 += __shfl_xor_sync(0xffffffffu, s2, 1);
                s2 += __shfl_xor_sync(0xffffffffu, s2, 2);
                lp += __shfl_xor_sync(0xffffffffu, lp, 1);
                lp += __shfl_xor_sync(0xffffffffu, lp, 2);
                if (q4 == 0) {
                    *(float2*)(sm + RED_O + (warp * 144 + r) * 8) = make_float2(s1, s2);
                    ((float*)(sm + LP_O))[warp * 144 + r] = lp;
                }
            }
        __syncthreads();

        // per-row finalize -> w = exp(l)*rstd  (max-free: l is bounded)
        if (tid < 144) {
            float s1 = 0.f, s2 = 0.f, lp = 0.f;
#pragma unroll
            for (int w = 0; w < 8; w++) {
                float2 v = *(float2*)(sm + RED_O + (w * 144 + tid) * 8);
                s1 += v.x; s2 += v.y;
                lp += ((float*)(sm + LP_O))[w * 144 + tid];
            }
            float mu = s1 * (1.0f / 128.0f);
            float var = fmaf(s2, 1.0f / 128.0f, -mu * mu);
            float rstd = rsqrtf(var + 1e-5f);
            float l = fmaf(rstd, lp - mu * S1, S2);
            float e = __expf(l);
            rs_s += e;
            float w = e * rstd;
            rs_q = fmaf(w, mu, rs_q);
            ((float*)(sm + RAB_O))[tid] = w;
        }
        if (more) { stsX(0); ldgX(t + 1, 1); }   // overlap with finalize/barrier
        __syncthreads();

        // P += w * h   (h reloaded from own SMEM slots; exact to 2^-17)
#pragma unroll
        for (int mt = 0; mt < 9; mt++)
#pragma unroll
            for (int rh = 0; rh < 2; rh++) {
                int r = mt * 16 + g + rh * 8;
                float w = ((float*)(sm + RAB_O))[r];
                uint32_t p0 = *(uint32_t*)(sm + H_HI + hswz(r, cA));
                uint32_t p1 = *(uint32_t*)(sm + H_HI + hswz(r, cA + 8));
                uint32_t l0 = *(uint32_t*)(sm + H_LO + hswz(r, cA));
                uint32_t l1 = *(uint32_t*)(sm + H_LO + hswz(r, cA + 8));
                float v0 = __uint_as_float(p0 << 16)        + __uint_as_float(l0 << 16);
                float v1 = __uint_as_float(p0 & 0xffff0000u) + __uint_as_float(l0 & 0xffff0000u);
                float v2 = __uint_as_float(p1 << 16)        + __uint_as_float(l1 << 16);
                float v3 = __uint_as_float(p1 & 0xffff0000u) + __uint_as_float(l1 & 0xffff0000u);
                P[mt][0][rh * 2]     = fmaf(w, v0, P[mt][0][rh * 2]);
                P[mt][0][rh * 2 + 1] = fmaf(w, v1, P[mt][0][rh * 2 + 1]);
                P[mt][1][rh * 2]     = fmaf(w, v2, P[mt][1][rh * 2]);
                P[mt][1][rh * 2 + 1] = fmaf(w, v3, P[mt][1][rh * 2 + 1]);
            }

        if (more) { stsX(1); ldgX(t + 1, 2); stsX(2); }
        __syncthreads();   // x tiles ready; RED/LP/RAB reusable
    }

    // ---- final: out = (Σ Wd·γ·P − q·Σ(Wd·γ))/s + Σ(Wd·β) + dense_b ----
    if (tid < CC) {
        float wg = 0.f, wb = 0.f;
        for (int k = 0; k < 128; k++) {
            float wd = dense_W[tid * 128 + k];
            wg += wd * ln_g[k];
            wb += wd * ln_b[k];
        }
        ((float*)(sm + WGS_O))[tid] = wg;
        ((float*)(sm + WB_O))[tid] = wb;
    }
    {
        float g0 = ln_g[cA], g1 = ln_g[cA + 1], g2 = ln_g[cA + 8], g3 = ln_g[cA + 9];
        float wdg[CC][4];
#pragma unroll
        for (int c2 = 0; c2 < CC; c2++) {
            wdg[c2][0] = dense_W[c2 * 128 + cA] * g0;
            wdg[c2][1] = dense_W[c2 * 128 + cA + 1] * g1;
            wdg[c2][2] = dense_W[c2 * 128 + cA + 8] * g2;
            wdg[c2][3] = dense_W[c2 * 128 + cA + 9] * g3;
        }
        // OUTS overlay in X region: [8][144][10] fp32
#pragma unroll
        for (int mt = 0; mt < 9; mt++)
#pragma unroll
            for (int rh = 0; rh < 2; rh++) {
                int r = mt * 16 + g + rh * 8;
                float pv0 = P[mt][0][rh * 2], pv1 = P[mt][0][rh * 2 + 1];
                float pv2 = P[mt][1][rh * 2], pv3 = P[mt][1][rh * 2 + 1];
#pragma unroll
                for (int c2 = 0; c2 < CC; c2++) {
                    float s = fmaf(pv0, wdg[c2][0], fmaf(pv1, wdg[c2][1],
                              fmaf(pv2, wdg[c2][2], pv3 * wdg[c2][3])));
                    s += __shfl_xor_sync(0xffffffffu, s, 1);
                    s += __shfl_xor_sync(0xffffffffu, s, 2);
                    if (q4 == 0)
                        ((float*)(sm + X_HI))[(warp * 144 + r) * CC + c2] = s;
                }
            }
    }
    __syncthreads();
    if (tid < 144 && (n0 + tid) < NN) {
        float inv = 1.0f / rs_s;
#pragma unroll
        for (int c2 = 0; c2 < CC; c2++) {
            float tot = 0.f;
#pragma unroll
            for (int w = 0; w < 8; w++)
                tot += ((float*)(sm + X_HI))[(w * 144 + tid) * CC + c2];
            float val = (tot - rs_q * ((float*)(sm + WGS_O))[c2]) * inv
                        + ((float*)(sm + WB_O))[c2] + dense_b[c2];
            out[(n0 + tid) * CC + c2] = val;
        }
    }
}

// ===========================================================================
extern "C" void kernel_launch(void* const* d_in, const int* in_sizes, int n_in,
                              void* d_out, int out_size)
{
    const float* X       = (const float*)d_in[0];
    const float* W_ih    = (const float*)d_in[1];
    const float* W_hh    = (const float*)d_in[2];
    const float* b_ih    = (const float*)d_in[3];
    const float* b_hh    = (const float*)d_in[4];
    const float* ln_g    = (const float*)d_in[5];
    const float* ln_b    = (const float*)d_in[6];
    const float* attn_W  = (const float*)d_in[7];
    const float* attn_b  = (const float*)d_in[8];
    const float* dense_W = (const float*)d_in[9];
    const float* dense_b = (const float*)d_in[10];
    float* out = (float*)d_out;

    cudaFuncSetAttribute(grn_one, cudaFuncAttributeMaxDynamicSharedMemorySize, SMEMSZ);

    grn_one<<<(NN + 143) / 144, 256, SMEMSZ>>>(
        X, W_ih, W_hh, b_ih, b_hh, ln_g, ln_b, attn_W, attn_b,
        dense_W, dense_b, out);
}